// round 12
// baseline (speedup 1.0000x reference)
#include <cuda_runtime.h>
#include <cuda_bf16.h>
#include <cstdint>
#include <cstddef>

#define TT_   512
#define BB_   256
#define HID   128
#define GATE  512

__device__ float g_h1 [(size_t)TT_ * BB_ * 2 * HID];
__device__ float g_g1f[(size_t)TT_ * BB_ * GATE];
__device__ float g_h2f[BB_ * HID];

__device__ __forceinline__ float sigm_f(float x) { return __fdividef(1.0f, 1.0f + __expf(-x)); }
__device__ __forceinline__ float tanh_f(float x) {
    float a = fabsf(x), e = __expf(-2.0f * a);
    return copysignf(__fdividef(1.0f - e, 1.0f + e), x);
}
__device__ __forceinline__ void bsplit(float f0, float f1, uint32_t& h2, uint32_t& l2) {
    asm("cvt.rn.bf16x2.f32 %0, %1, %2;" : "=r"(h2) : "f"(f1), "f"(f0));
    float r0 = f0 - __uint_as_float(h2 << 16);
    float r1 = f1 - __uint_as_float(h2 & 0xffff0000u);
    asm("cvt.rn.bf16x2.f32 %0, %1, %2;" : "=r"(l2) : "f"(r1), "f"(r0));
}
__device__ __forceinline__ void mma16816(float* d, uint32_t a0, uint32_t a1, uint32_t a2, uint32_t a3,
                                         uint32_t b0, uint32_t b1) {
    asm volatile("mma.sync.aligned.m16n8k16.row.col.f32.bf16.bf16.f32 "
                 "{%0,%1,%2,%3}, {%4,%5,%6,%7}, {%8,%9}, {%0,%1,%2,%3};"
                 : "+f"(d[0]), "+f"(d[1]), "+f"(d[2]), "+f"(d[3])
                 : "r"(a0), "r"(a1), "r"(a2), "r"(a3), "r"(b0), "r"(b1));
}

// ============ Kernel 1: layer-0 recurrence — MMA + register-local cells ============
// grid (64,2), 512 thr. Warp w owns N-blocks {w, w+16, w+32, w+48} (cols w*8.. of i,f,g,o)
// so thread (gid<4, tig) holds all 4 gates of cells (w*8+tig*2{,+1}, b=gid) in registers.
// Double-buffered A (hi/lo bf16), ONE __syncthreads per step.
#define L0_XS 0                      // x slice  [512][12] f32   24576
#define L0_WI 24576                  // Wih+b    [512][4]  f32    8192
#define L0_WH 32768                  // Whi u32  [512][68]      139264
#define L0_AB 172032                 // A bufs   [2][2][16][68] u32  17408
#define L0_SM 189440

extern "C" __global__ void __launch_bounds__(512, 1)
lstm_l0(const float* __restrict__ x,
        const float* __restrict__ Wih_f, const float* __restrict__ Whh_f, const float* __restrict__ bv_f,
        const float* __restrict__ Wih_b, const float* __restrict__ Whh_b, const float* __restrict__ bv_b)
{
    extern __shared__ char smraw[];
    float*    xsm  = reinterpret_cast<float*>(smraw + L0_XS);
    float*    wihs = reinterpret_cast<float*>(smraw + L0_WI);
    uint32_t* Whi  = reinterpret_cast<uint32_t*>(smraw + L0_WH);
    uint32_t* Abuf = reinterpret_cast<uint32_t*>(smraw + L0_AB);  // [pb][hi|lo][16][68]

    const int tid = threadIdx.x;
    const int dir = blockIdx.y, b0 = blockIdx.x * 4;
    const float* __restrict__ Wih = dir ? Wih_b : Wih_f;
    const float* __restrict__ Whh = dir ? Whh_b : Whh_f;
    const float* __restrict__ bv  = dir ? bv_b  : bv_f;

    const int wid = tid >> 5, lane = tid & 31;
    const int gid = lane >> 2, tig = lane & 3;
    const int u0 = wid * 8 + tig * 2;          // first owned cell unit

    // Whi -> smem
    for (int idx = tid; idx < 512 * 64; idx += 512) {
        int j = idx >> 6, kp = idx & 63;
        float2 w = *reinterpret_cast<const float2*>(Whh + j * 128 + kp * 2);
        uint32_t h2, l2; bsplit(w.x, w.y, h2, l2);
        Whi[j * 68 + kp] = h2;
    }
    // Wlo fragments (regs), j = q*128 + wid*8 + gid
    uint32_t wlo[4][8][2];
#pragma unroll
    for (int q = 0; q < 4; q++) {
        const float* wr = Whh + (q * 128 + wid * 8 + gid) * 128;
#pragma unroll
        for (int ks = 0; ks < 8; ks++) {
            int k = ks * 16 + tig * 2;
            float2 wa = *reinterpret_cast<const float2*>(wr + k);
            float2 wb = *reinterpret_cast<const float2*>(wr + k + 8);
            uint32_t h2, l2;
            bsplit(wa.x, wa.y, h2, l2); wlo[q][ks][0] = l2;
            bsplit(wb.x, wb.y, h2, l2); wlo[q][ks][1] = l2;
        }
    }
    // Wih + bias
    wihs[tid * 4 + 0] = Wih[tid * 3 + 0];
    wihs[tid * 4 + 1] = Wih[tid * 3 + 1];
    wihs[tid * 4 + 2] = Wih[tid * 3 + 2];
    wihs[tid * 4 + 3] = bv[tid];
    // full x slice: xsm[t][r][i]
    for (int idx = tid; idx < 6144; idx += 512) {
        int r = idx / 1536, rem = idx - r * 1536;
        xsm[(rem / 3) * 12 + r * 3 + (rem % 3)] = x[(size_t)(b0 + r) * 1536 + rem];
    }
    // zero both A buffers (pad rows stay zero forever)
    for (int idx = tid; idx < 2 * 2 * 16 * 68; idx += 512) Abuf[idx] = 0u;

    float c0 = 0.0f, c1 = 0.0f;
    __syncthreads();

    for (int s = 0; s < TT_; s++) {
        const int tcur = dir ? (TT_ - 1 - s) : s;
        const int pb = s & 1;
        const uint32_t* Ah = Abuf + pb * 2176;
        const uint32_t* Al = Ah + 1088;

        float acc[4][4];
#pragma unroll
        for (int q = 0; q < 4; q++) { acc[q][0] = acc[q][1] = acc[q][2] = acc[q][3] = 0.0f; }
#pragma unroll
        for (int ks = 0; ks < 8; ks++) {
            const int abase = gid * 68 + ks * 8 + tig;
            uint32_t ah0 = Ah[abase],     ah1 = Ah[abase + 544];
            uint32_t ah2 = Ah[abase + 4], ah3 = Ah[abase + 548];
            uint32_t al0 = Al[abase],     al1 = Al[abase + 544];
            uint32_t al2 = Al[abase + 4], al3 = Al[abase + 548];
#pragma unroll
            for (int q = 0; q < 4; q++) {
                const int bbase = (q * 128 + wid * 8 + gid) * 68 + ks * 8 + tig;
                uint32_t bh0 = Whi[bbase], bh1 = Whi[bbase + 4];
                mma16816(acc[q], ah0, ah1, ah2, ah3, bh0, bh1);
                mma16816(acc[q], al0, al1, al2, al3, bh0, bh1);
                mma16816(acc[q], ah0, ah1, ah2, ah3, wlo[q][ks][0], wlo[q][ks][1]);
            }
        }

        if (gid < 4) {                         // real rows: cells fully register-local
            const float* xp = xsm + tcur * 12 + gid * 3;
            float x0 = xp[0], x1 = xp[1], x2 = xp[2];
            float pre[4][2];
#pragma unroll
            for (int q = 0; q < 4; q++) {
                int j = q * 128 + u0;
                float4 w0 = *reinterpret_cast<const float4*>(wihs + j * 4);
                float4 w1 = *reinterpret_cast<const float4*>(wihs + (j + 1) * 4);
                pre[q][0] = acc[q][0] + fmaf(w0.x, x0, fmaf(w0.y, x1, fmaf(w0.z, x2, w0.w)));
                pre[q][1] = acc[q][1] + fmaf(w1.x, x0, fmaf(w1.y, x1, fmaf(w1.z, x2, w1.w)));
            }
            c0 = sigm_f(pre[1][0]) * c0 + sigm_f(pre[0][0]) * tanh_f(pre[2][0]);
            float h0 = sigm_f(pre[3][0]) * tanh_f(c0);
            c1 = sigm_f(pre[1][1]) * c1 + sigm_f(pre[0][1]) * tanh_f(pre[2][1]);
            float h1 = sigm_f(pre[3][1]) * tanh_f(c1);

            uint32_t h2, l2; bsplit(h0, h1, h2, l2);
            uint32_t* AhN = Abuf + (pb ^ 1) * 2176;
            AhN[gid * 68 + (u0 >> 1)]        = h2;
            AhN[1088 + gid * 68 + (u0 >> 1)] = l2;
            *reinterpret_cast<float2*>(
                g_h1 + ((size_t)tcur * BB_ + b0 + gid) * 256 + dir * 128 + u0) =
                make_float2(h0, h1);
        }
        __syncthreads();
    }
}

// ============ Kernel 3: layer-1 recurrence — same scheme, 2 real rows, gates from g_g1f ============
#define L1_WH 0                       // Whi u32 [512][68]  139264
#define L1_AB 139264                  // A bufs  [2][2][16][68] u32 17408
#define L1_SM 156672

extern "C" __global__ void __launch_bounds__(512, 1)
lstm_l1(const float* __restrict__ Whh)
{
    extern __shared__ char smraw[];
    uint32_t* Whi  = reinterpret_cast<uint32_t*>(smraw + L1_WH);
    uint32_t* Abuf = reinterpret_cast<uint32_t*>(smraw + L1_AB);

    const int tid = threadIdx.x;
    const int b0  = blockIdx.x * 2;
    const int wid = tid >> 5, lane = tid & 31;
    const int gid = lane >> 2, tig = lane & 3;
    const int u0 = wid * 8 + tig * 2;

    for (int idx = tid; idx < 512 * 64; idx += 512) {
        int j = idx >> 6, kp = idx & 63;
        float2 w = *reinterpret_cast<const float2*>(Whh + j * 128 + kp * 2);
        uint32_t h2, l2; bsplit(w.x, w.y, h2, l2);
        Whi[j * 68 + kp] = h2;
    }
    uint32_t wlo[4][8][2];
#pragma unroll
    for (int q = 0; q < 4; q++) {
        const float* wr = Whh + (q * 128 + wid * 8 + gid) * 128;
#pragma unroll
        for (int ks = 0; ks < 8; ks++) {
            int k = ks * 16 + tig * 2;
            float2 wa = *reinterpret_cast<const float2*>(wr + k);
            float2 wb = *reinterpret_cast<const float2*>(wr + k + 8);
            uint32_t h2, l2;
            bsplit(wa.x, wa.y, h2, l2); wlo[q][ks][0] = l2;
            bsplit(wb.x, wb.y, h2, l2); wlo[q][ks][1] = l2;
        }
    }
    for (int idx = tid; idx < 2 * 2 * 16 * 68; idx += 512) Abuf[idx] = 0u;

    float c0 = 0.0f, c1 = 0.0f;
    __syncthreads();

    for (int s = 0; s < TT_; s++) {
        const int pb = s & 1;
        const uint32_t* Ah = Abuf + pb * 2176;
        const uint32_t* Al = Ah + 1088;

        // prefetch this step's precomputed input gates (latency hidden by MMA phase)
        float2 pg[4];
        if (gid < 2) {
            const float* gp = g_g1f + ((size_t)s * BB_ + b0 + gid) * GATE + u0;
#pragma unroll
            for (int q = 0; q < 4; q++)
                pg[q] = *reinterpret_cast<const float2*>(gp + q * 128);
        }

        float acc[4][4];
#pragma unroll
        for (int q = 0; q < 4; q++) { acc[q][0] = acc[q][1] = acc[q][2] = acc[q][3] = 0.0f; }
#pragma unroll
        for (int ks = 0; ks < 8; ks++) {
            const int abase = gid * 68 + ks * 8 + tig;
            uint32_t ah0 = Ah[abase],     ah1 = Ah[abase + 544];
            uint32_t ah2 = Ah[abase + 4], ah3 = Ah[abase + 548];
            uint32_t al0 = Al[abase],     al1 = Al[abase + 544];
            uint32_t al2 = Al[abase + 4], al3 = Al[abase + 548];
#pragma unroll
            for (int q = 0; q < 4; q++) {
                const int bbase = (q * 128 + wid * 8 + gid) * 68 + ks * 8 + tig;
                uint32_t bh0 = Whi[bbase], bh1 = Whi[bbase + 4];
                mma16816(acc[q], ah0, ah1, ah2, ah3, bh0, bh1);
                mma16816(acc[q], al0, al1, al2, al3, bh0, bh1);
                mma16816(acc[q], ah0, ah1, ah2, ah3, wlo[q][ks][0], wlo[q][ks][1]);
            }
        }

        if (gid < 2) {
            float pre[4][2];
#pragma unroll
            for (int q = 0; q < 4; q++) {
                pre[q][0] = acc[q][0] + pg[q].x;
                pre[q][1] = acc[q][1] + pg[q].y;
            }
            c0 = sigm_f(pre[1][0]) * c0 + sigm_f(pre[0][0]) * tanh_f(pre[2][0]);
            float h0 = sigm_f(pre[3][0]) * tanh_f(c0);
            c1 = sigm_f(pre[1][1]) * c1 + sigm_f(pre[0][1]) * tanh_f(pre[2][1]);
            float h1 = sigm_f(pre[3][1]) * tanh_f(c1);

            uint32_t h2, l2; bsplit(h0, h1, h2, l2);
            uint32_t* AhN = Abuf + (pb ^ 1) * 2176;
            AhN[gid * 68 + (u0 >> 1)]        = h2;
            AhN[1088 + gid * 68 + (u0 >> 1)] = l2;
            if (s == TT_ - 1)
                *reinterpret_cast<float2*>(g_h2f + (b0 + gid) * HID + u0) = make_float2(h0, h1);
        }
        __syncthreads();
    }
}

// ============ Kernel 2: GEMM via bf16 tensor cores (R10/R11 measured-pass) ============
#define WPB 264
extern "C" __global__ void __launch_bounds__(256, 1)
gemm_l1in(const float* __restrict__ W, const float* __restrict__ bias)
{
    extern __shared__ __nv_bfloat16 smb[];
    __nv_bfloat16* Whi = smb;
    __nv_bfloat16* Wlo = Whi + 128 * WPB;
    __nv_bfloat16* Ahi = Wlo + 128 * WPB;
    __nv_bfloat16* Alo = Ahi + 64 * WPB;
    float* biasS = reinterpret_cast<float*>(Alo + 64 * WPB);

    const int tid = threadIdx.x;
    const int jblk = blockIdx.x & 3, tg = blockIdx.x >> 2;

    for (int idx = tid; idx < 128 * 128; idx += 256) {
        int jj = idx >> 7, kp = idx & 127;
        float2 w = *reinterpret_cast<const float2*>(W + ((size_t)(jblk * 128 + jj)) * 256 + 2 * kp);
        uint32_t h2, l2; bsplit(w.x, w.y, h2, l2);
        *reinterpret_cast<uint32_t*>(Whi + jj * WPB + 2 * kp) = h2;
        *reinterpret_cast<uint32_t*>(Wlo + jj * WPB + 2 * kp) = l2;
    }
    if (tid < 128) biasS[tid] = bias[jblk * 128 + tid];

    const int wid = tid >> 5, lane = tid & 31;
    const int wm = wid >> 1, wn = wid & 1;
    const int m0 = wm * 16, n0 = wn * 64;
    const int gid = lane >> 2, tig = lane & 3;
    __syncthreads();

    for (int tile = tg; tile < 2048; tile += 37) {
        const size_t r0 = (size_t)tile * 64;
        for (int idx = tid; idx < 64 * 128; idx += 256) {
            int row = idx >> 7, kp = idx & 127;
            float2 a = *reinterpret_cast<const float2*>(g_h1 + (r0 + row) * 256 + 2 * kp);
            uint32_t h2, l2; bsplit(a.x, a.y, h2, l2);
            *reinterpret_cast<uint32_t*>(Ahi + row * WPB + 2 * kp) = h2;
            *reinterpret_cast<uint32_t*>(Alo + row * WPB + 2 * kp) = l2;
        }
        __syncthreads();

        float acc[8][4];
#pragma unroll
        for (int nf = 0; nf < 8; nf++) {
            float bv0 = biasS[n0 + nf * 8 + tig * 2], bv1 = biasS[n0 + nf * 8 + tig * 2 + 1];
            acc[nf][0] = bv0; acc[nf][1] = bv1; acc[nf][2] = bv0; acc[nf][3] = bv1;
        }
#pragma unroll 4
        for (int ks = 0; ks < 16; ks++) {
            const int k0 = ks * 16;
            const __nv_bfloat16* arow = Ahi + (m0 + gid) * WPB + k0 + tig * 2;
            const __nv_bfloat16* arowl = Alo + (m0 + gid) * WPB + k0 + tig * 2;
            uint32_t ah0 = *reinterpret_cast<const uint32_t*>(arow);
            uint32_t ah1 = *reinterpret_cast<const uint32_t*>(arow + 8 * WPB);
            uint32_t ah2 = *reinterpret_cast<const uint32_t*>(arow + 8);
            uint32_t ah3 = *reinterpret_cast<const uint32_t*>(arow + 8 * WPB + 8);
            uint32_t al0 = *reinterpret_cast<const uint32_t*>(arowl);
            uint32_t al1 = *reinterpret_cast<const uint32_t*>(arowl + 8 * WPB);
            uint32_t al2 = *reinterpret_cast<const uint32_t*>(arowl + 8);
            uint32_t al3 = *reinterpret_cast<const uint32_t*>(arowl + 8 * WPB + 8);
#pragma unroll
            for (int nf = 0; nf < 8; nf++) {
                const __nv_bfloat16* brow = Whi + (n0 + nf * 8 + gid) * WPB + k0 + tig * 2;
                const __nv_bfloat16* browl = Wlo + (n0 + nf * 8 + gid) * WPB + k0 + tig * 2;
                uint32_t bh0 = *reinterpret_cast<const uint32_t*>(brow);
                uint32_t bh1 = *reinterpret_cast<const uint32_t*>(brow + 8);
                uint32_t bl0 = *reinterpret_cast<const uint32_t*>(browl);
                uint32_t bl1 = *reinterpret_cast<const uint32_t*>(browl + 8);
                mma16816(acc[nf], ah0, ah1, ah2, ah3, bh0, bh1);
                mma16816(acc[nf], al0, al1, al2, al3, bh0, bh1);
                mma16816(acc[nf], ah0, ah1, ah2, ah3, bl0, bl1);
            }
        }
        const size_t row = r0 + m0 + gid;
        const int col = jblk * 128 + n0 + tig * 2;
#pragma unroll
        for (int nf = 0; nf < 8; nf++) {
            *reinterpret_cast<float2*>(g_g1f + row * GATE + col + nf * 8) =
                make_float2(acc[nf][0], acc[nf][1]);
            *reinterpret_cast<float2*>(g_g1f + (row + 8) * GATE + col + nf * 8) =
                make_float2(acc[nf][2], acc[nf][3]);
        }
        __syncthreads();
    }
}

// ============ Kernel 4: layer-1 backward one step + FC (measured-pass) ============
extern "C" __global__ void __launch_bounds__(512, 1)
final_k(const float* __restrict__ Wihb, const float* __restrict__ bvb,
        const float* __restrict__ Wfc,  const float* __restrict__ bfc,
        float* __restrict__ out)
{
    __shared__ float h1s[1024], hfs[512], gates[2048], hbs[512];
    const int tid = threadIdx.x, b0 = blockIdx.x * 4;

    for (int idx = tid; idx < 1024; idx += 512) {
        int r = idx >> 8, k = idx & 255;
        h1s[idx] = g_h1[((size_t)(TT_ - 1) * BB_ + b0 + r) * 256 + k];
    }
    if (tid < 512) hfs[tid] = g_h2f[b0 * HID + tid];
    __syncthreads();

    float acc[4];
    const float bj = bvb[tid];
#pragma unroll
    for (int r = 0; r < 4; r++) acc[r] = bj;
    const float* wr = Wihb + (size_t)tid * 256;
#pragma unroll 4
    for (int k = 0; k < 256; k++) {
        float w = wr[k];
#pragma unroll
        for (int r = 0; r < 4; r++) acc[r] = fmaf(h1s[r * 256 + k], w, acc[r]);
    }
#pragma unroll
    for (int r = 0; r < 4; r++) gates[r * 512 + tid] = acc[r];
    __syncthreads();
    {
        int r = tid >> 7, u = tid & 127;
        float c = sigm_f(gates[r * 512 + u]) * tanh_f(gates[r * 512 + u + 256]);
        hbs[r * 128 + u] = sigm_f(gates[r * 512 + u + 384]) * tanh_f(c);
    }
    __syncthreads();
    if (tid < 24) {
        int r = tid / 6, o = tid % 6;
        const float* wf = Wfc + o * 256;
        float s0 = bfc[o], s1 = 0.0f;
#pragma unroll 4
        for (int jj = 0; jj < 128; jj++) {
            s0 = fmaf(hfs[r * 128 + jj], wf[jj], s0);
            s1 = fmaf(hbs[r * 128 + jj], wf[128 + jj], s1);
        }
        out[(b0 + r) * 6 + o] = s0 + s1;
    }
}

extern "C" void kernel_launch(void* const* d_in, const int* in_sizes, int n_in,
                              void* d_out, int out_size)
{
    (void)in_sizes; (void)n_in; (void)out_size;
    const float* x     = (const float*)d_in[0];
    const float* Wih0f = (const float*)d_in[1];
    const float* Whh0f = (const float*)d_in[2];
    const float* b0f   = (const float*)d_in[3];
    const float* Wih0b = (const float*)d_in[4];
    const float* Whh0b = (const float*)d_in[5];
    const float* b0b   = (const float*)d_in[6];
    const float* Wih1f = (const float*)d_in[7];
    const float* Whh1f = (const float*)d_in[8];
    const float* b1f   = (const float*)d_in[9];
    const float* Wih1b = (const float*)d_in[10];
    const float* Whh1b = (const float*)d_in[11];
    const float* b1b   = (const float*)d_in[12];
    const float* Wfc   = (const float*)d_in[13];
    const float* bfc   = (const float*)d_in[14];
    float* out = (float*)d_out;

    const int SM_L0 = L0_SM;                                       // 189,440 B
    const int SM_G  = (2 * 128 * WPB + 2 * 64 * WPB) * 2 + 512;    // 203,264 B
    const int SM_L1 = L1_SM;                                       // 156,672 B

    cudaFuncSetAttribute(lstm_l0,   cudaFuncAttributeMaxDynamicSharedMemorySize, SM_L0);
    cudaFuncSetAttribute(gemm_l1in, cudaFuncAttributeMaxDynamicSharedMemorySize, SM_G);
    cudaFuncSetAttribute(lstm_l1,   cudaFuncAttributeMaxDynamicSharedMemorySize, SM_L1);

    lstm_l0<<<dim3(64, 2), 512, SM_L0>>>(x, Wih0f, Whh0f, b0f, Wih0b, Whh0b, b0b);
    gemm_l1in<<<148, 256, SM_G>>>(Wih1f, b1f);
    lstm_l1<<<128, 512, SM_L1>>>(Whh1f);
    final_k<<<64, 512>>>(Wih1b, b1b, Wfc, bfc, out);
}

// round 13
// speedup vs baseline: 1.0963x; 1.0963x over previous
#include <cuda_runtime.h>
#include <cuda_bf16.h>
#include <cstdint>
#include <cstddef>

#define TT_   512
#define BB_   256
#define HID   128
#define GATE  512
#define KSMH  36
#define KRGH  28

__device__ float g_h1 [(size_t)TT_ * BB_ * 2 * HID];
__device__ float g_g1f[(size_t)TT_ * BB_ * GATE];
__device__ float g_h2f[BB_ * HID];

__device__ __forceinline__ unsigned long long pack2(float lo, float hi) {
    unsigned long long r; asm("mov.b64 %0, {%1, %2};" : "=l"(r) : "f"(lo), "f"(hi)); return r;
}
__device__ __forceinline__ void ffma2(unsigned long long& d, unsigned long long a, unsigned long long b) {
    asm("fma.rn.f32x2 %0, %1, %2, %0;" : "+l"(d) : "l"(a), "l"(b));
}
__device__ __forceinline__ float sigm_f(float x) { return __fdividef(1.0f, 1.0f + __expf(-x)); }
__device__ __forceinline__ float tanh_f(float x) {
    float a = fabsf(x), e = __expf(-2.0f * a);
    return copysignf(__fdividef(1.0f - e, 1.0f + e), x);
}
__device__ __forceinline__ void bsplit(float f0, float f1, uint32_t& h2, uint32_t& l2) {
    asm("cvt.rn.bf16x2.f32 %0, %1, %2;" : "=r"(h2) : "f"(f1), "f"(f0));
    float r0 = f0 - __uint_as_float(h2 << 16);
    float r1 = f1 - __uint_as_float(h2 & 0xffff0000u);
    asm("cvt.rn.bf16x2.f32 %0, %1, %2;" : "=r"(l2) : "f"(r1), "f"(r0));
}
__device__ __forceinline__ void mma16816(float* d, uint32_t a0, uint32_t a1, uint32_t a2, uint32_t a3,
                                         uint32_t b0, uint32_t b1) {
    asm volatile("mma.sync.aligned.m16n8k16.row.col.f32.bf16.bf16.f32 "
                 "{%0,%1,%2,%3}, {%4,%5,%6,%7}, {%8,%9}, {%0,%1,%2,%3};"
                 : "+f"(d[0]), "+f"(d[1]), "+f"(d[2]), "+f"(d[3])
                 : "r"(a0), "r"(a1), "r"(a2), "r"(a3), "r"(b0), "r"(b1));
}

// ============ Kernel 1: layer-0 recurrence — MMA + register-local cells (R12) ============
#define L0_XS 0
#define L0_WI 24576
#define L0_WH 32768
#define L0_AB 172032
#define L0_SM 189440

extern "C" __global__ void __launch_bounds__(512, 1)
lstm_l0(const float* __restrict__ x,
        const float* __restrict__ Wih_f, const float* __restrict__ Whh_f, const float* __restrict__ bv_f,
        const float* __restrict__ Wih_b, const float* __restrict__ Whh_b, const float* __restrict__ bv_b)
{
    extern __shared__ char smraw[];
    float*    xsm  = reinterpret_cast<float*>(smraw + L0_XS);
    float*    wihs = reinterpret_cast<float*>(smraw + L0_WI);
    uint32_t* Whi  = reinterpret_cast<uint32_t*>(smraw + L0_WH);
    uint32_t* Abuf = reinterpret_cast<uint32_t*>(smraw + L0_AB);

    const int tid = threadIdx.x;
    const int dir = blockIdx.y, b0 = blockIdx.x * 4;
    const float* __restrict__ Wih = dir ? Wih_b : Wih_f;
    const float* __restrict__ Whh = dir ? Whh_b : Whh_f;
    const float* __restrict__ bv  = dir ? bv_b  : bv_f;

    const int wid = tid >> 5, lane = tid & 31;
    const int gid = lane >> 2, tig = lane & 3;
    const int u0 = wid * 8 + tig * 2;

    for (int idx = tid; idx < 512 * 64; idx += 512) {
        int j = idx >> 6, kp = idx & 63;
        float2 w = *reinterpret_cast<const float2*>(Whh + j * 128 + kp * 2);
        uint32_t h2, l2; bsplit(w.x, w.y, h2, l2);
        Whi[j * 68 + kp] = h2;
    }
    uint32_t wlo[4][8][2];
#pragma unroll
    for (int q = 0; q < 4; q++) {
        const float* wr = Whh + (q * 128 + wid * 8 + gid) * 128;
#pragma unroll
        for (int ks = 0; ks < 8; ks++) {
            int k = ks * 16 + tig * 2;
            float2 wa = *reinterpret_cast<const float2*>(wr + k);
            float2 wb = *reinterpret_cast<const float2*>(wr + k + 8);
            uint32_t h2, l2;
            bsplit(wa.x, wa.y, h2, l2); wlo[q][ks][0] = l2;
            bsplit(wb.x, wb.y, h2, l2); wlo[q][ks][1] = l2;
        }
    }
    wihs[tid * 4 + 0] = Wih[tid * 3 + 0];
    wihs[tid * 4 + 1] = Wih[tid * 3 + 1];
    wihs[tid * 4 + 2] = Wih[tid * 3 + 2];
    wihs[tid * 4 + 3] = bv[tid];
    for (int idx = tid; idx < 6144; idx += 512) {
        int r = idx / 1536, rem = idx - r * 1536;
        xsm[(rem / 3) * 12 + r * 3 + (rem % 3)] = x[(size_t)(b0 + r) * 1536 + rem];
    }
    for (int idx = tid; idx < 2 * 2 * 16 * 68; idx += 512) Abuf[idx] = 0u;

    float c0 = 0.0f, c1 = 0.0f;
    __syncthreads();

    for (int s = 0; s < TT_; s++) {
        const int tcur = dir ? (TT_ - 1 - s) : s;
        const int pb = s & 1;
        const uint32_t* Ah = Abuf + pb * 2176;
        const uint32_t* Al = Ah + 1088;

        float acc[4][4];
#pragma unroll
        for (int q = 0; q < 4; q++) { acc[q][0] = acc[q][1] = acc[q][2] = acc[q][3] = 0.0f; }
#pragma unroll
        for (int ks = 0; ks < 8; ks++) {
            const int abase = gid * 68 + ks * 8 + tig;
            uint32_t ah0 = Ah[abase],     ah1 = Ah[abase + 544];
            uint32_t ah2 = Ah[abase + 4], ah3 = Ah[abase + 548];
            uint32_t al0 = Al[abase],     al1 = Al[abase + 544];
            uint32_t al2 = Al[abase + 4], al3 = Al[abase + 548];
#pragma unroll
            for (int q = 0; q < 4; q++) {
                const int bbase = (q * 128 + wid * 8 + gid) * 68 + ks * 8 + tig;
                uint32_t bh0 = Whi[bbase], bh1 = Whi[bbase + 4];
                mma16816(acc[q], ah0, ah1, ah2, ah3, bh0, bh1);
                mma16816(acc[q], al0, al1, al2, al3, bh0, bh1);
                mma16816(acc[q], ah0, ah1, ah2, ah3, wlo[q][ks][0], wlo[q][ks][1]);
            }
        }

        if (gid < 4) {
            const float* xp = xsm + tcur * 12 + gid * 3;
            float x0 = xp[0], x1 = xp[1], x2 = xp[2];
            float pre[4][2];
#pragma unroll
            for (int q = 0; q < 4; q++) {
                int j = q * 128 + u0;
                float4 w0 = *reinterpret_cast<const float4*>(wihs + j * 4);
                float4 w1 = *reinterpret_cast<const float4*>(wihs + (j + 1) * 4);
                pre[q][0] = acc[q][0] + fmaf(w0.x, x0, fmaf(w0.y, x1, fmaf(w0.z, x2, w0.w)));
                pre[q][1] = acc[q][1] + fmaf(w1.x, x0, fmaf(w1.y, x1, fmaf(w1.z, x2, w1.w)));
            }
            c0 = sigm_f(pre[1][0]) * c0 + sigm_f(pre[0][0]) * tanh_f(pre[2][0]);
            float h0 = sigm_f(pre[3][0]) * tanh_f(c0);
            c1 = sigm_f(pre[1][1]) * c1 + sigm_f(pre[0][1]) * tanh_f(pre[2][1]);
            float h1 = sigm_f(pre[3][1]) * tanh_f(c1);

            uint32_t h2, l2; bsplit(h0, h1, h2, l2);
            uint32_t* AhN = Abuf + (pb ^ 1) * 2176;
            AhN[gid * 68 + (u0 >> 1)]        = h2;
            AhN[1088 + gid * 68 + (u0 >> 1)] = l2;
            *reinterpret_cast<float2*>(
                g_h1 + ((size_t)tcur * BB_ + b0 + gid) * 256 + dir * 128 + u0) =
                make_float2(h0, h1);
        }
        __syncthreads();
    }
}

// ============ Kernel 2: GEMM — bf16 MMA, now 512 threads (4 warps/SMSP) ============
#define WPB 264
extern "C" __global__ void __launch_bounds__(512, 1)
gemm_l1in(const float* __restrict__ W, const float* __restrict__ bias)
{
    extern __shared__ __nv_bfloat16 smb[];
    __nv_bfloat16* Whi = smb;
    __nv_bfloat16* Wlo = Whi + 128 * WPB;
    __nv_bfloat16* Ahi = Wlo + 128 * WPB;
    __nv_bfloat16* Alo = Ahi + 64 * WPB;
    float* biasS = reinterpret_cast<float*>(Alo + 64 * WPB);

    const int tid = threadIdx.x;
    const int jblk = blockIdx.x & 3, tg = blockIdx.x >> 2;

    for (int idx = tid; idx < 128 * 128; idx += 512) {
        int jj = idx >> 7, kp = idx & 127;
        float2 w = *reinterpret_cast<const float2*>(W + ((size_t)(jblk * 128 + jj)) * 256 + 2 * kp);
        uint32_t h2, l2; bsplit(w.x, w.y, h2, l2);
        *reinterpret_cast<uint32_t*>(Whi + jj * WPB + 2 * kp) = h2;
        *reinterpret_cast<uint32_t*>(Wlo + jj * WPB + 2 * kp) = l2;
    }
    if (tid < 128) biasS[tid] = bias[jblk * 128 + tid];

    const int wid = tid >> 5, lane = tid & 31;
    const int wm = wid >> 2, wn = wid & 3;          // 4 m-blocks x 4 n-blocks
    const int m0 = wm * 16, n0 = wn * 32;
    const int gid = lane >> 2, tig = lane & 3;
    __syncthreads();

    for (int tile = tg; tile < 2048; tile += 37) {
        const size_t r0 = (size_t)tile * 64;
        for (int idx = tid; idx < 64 * 128; idx += 512) {
            int row = idx >> 7, kp = idx & 127;
            float2 a = *reinterpret_cast<const float2*>(g_h1 + (r0 + row) * 256 + 2 * kp);
            uint32_t h2, l2; bsplit(a.x, a.y, h2, l2);
            *reinterpret_cast<uint32_t*>(Ahi + row * WPB + 2 * kp) = h2;
            *reinterpret_cast<uint32_t*>(Alo + row * WPB + 2 * kp) = l2;
        }
        __syncthreads();

        float acc[4][4];
#pragma unroll
        for (int nf = 0; nf < 4; nf++) {
            float bv0 = biasS[n0 + nf * 8 + tig * 2], bv1 = biasS[n0 + nf * 8 + tig * 2 + 1];
            acc[nf][0] = bv0; acc[nf][1] = bv1; acc[nf][2] = bv0; acc[nf][3] = bv1;
        }
#pragma unroll 4
        for (int ks = 0; ks < 16; ks++) {
            const int k0 = ks * 16;
            const __nv_bfloat16* arow  = Ahi + (m0 + gid) * WPB + k0 + tig * 2;
            const __nv_bfloat16* arowl = Alo + (m0 + gid) * WPB + k0 + tig * 2;
            uint32_t ah0 = *reinterpret_cast<const uint32_t*>(arow);
            uint32_t ah1 = *reinterpret_cast<const uint32_t*>(arow + 8 * WPB);
            uint32_t ah2 = *reinterpret_cast<const uint32_t*>(arow + 8);
            uint32_t ah3 = *reinterpret_cast<const uint32_t*>(arow + 8 * WPB + 8);
            uint32_t al0 = *reinterpret_cast<const uint32_t*>(arowl);
            uint32_t al1 = *reinterpret_cast<const uint32_t*>(arowl + 8 * WPB);
            uint32_t al2 = *reinterpret_cast<const uint32_t*>(arowl + 8);
            uint32_t al3 = *reinterpret_cast<const uint32_t*>(arowl + 8 * WPB + 8);
#pragma unroll
            for (int nf = 0; nf < 4; nf++) {
                const __nv_bfloat16* brow  = Whi + (n0 + nf * 8 + gid) * WPB + k0 + tig * 2;
                const __nv_bfloat16* browl = Wlo + (n0 + nf * 8 + gid) * WPB + k0 + tig * 2;
                uint32_t bh0 = *reinterpret_cast<const uint32_t*>(brow);
                uint32_t bh1 = *reinterpret_cast<const uint32_t*>(brow + 8);
                uint32_t bl0 = *reinterpret_cast<const uint32_t*>(browl);
                uint32_t bl1 = *reinterpret_cast<const uint32_t*>(browl + 8);
                mma16816(acc[nf], ah0, ah1, ah2, ah3, bh0, bh1);
                mma16816(acc[nf], al0, al1, al2, al3, bh0, bh1);
                mma16816(acc[nf], ah0, ah1, ah2, ah3, bl0, bl1);
            }
        }
        const size_t row = r0 + m0 + gid;
        const int col = jblk * 128 + n0 + tig * 2;
#pragma unroll
        for (int nf = 0; nf < 4; nf++) {
            *reinterpret_cast<float2*>(g_g1f + row * GATE + col + nf * 8) =
                make_float2(acc[nf][0], acc[nf][1]);
            *reinterpret_cast<float2*>(g_g1f + (row + 8) * GATE + col + nf * 8) =
                make_float2(acc[nf][2], acc[nf][3]);
        }
        __syncthreads();
    }
}

// ============ Kernel 3: layer-1 recurrence — FFMA2 split-k (REVERTED to measured-2890) ============
extern "C" __global__ void __launch_bounds__(512, 1)
lstm_l1(const float* __restrict__ Whh)
{
    extern __shared__ float sm1[];
    float* Wsm = sm1;
    float* hsm = sm1 + 2 * KSMH * 512;
    float* gsm = hsm + 1024;

    const int tid = threadIdx.x, g = tid >> 8, t = tid & 255, j0 = 2 * t;
    const int b0 = blockIdx.x * 2;

    for (int idx = tid; idx < 2 * KSMH * 512; idx += 512) {
        int gg = idx / (KSMH * 512), rem = idx - gg * (KSMH * 512);
        Wsm[idx] = Whh[(rem & 511) * HID + gg * 64 + (rem >> 9)];
    }
    unsigned long long wreg[KRGH];
#pragma unroll
    for (int r = 0; r < KRGH; r++) {
        int k = g * 64 + KSMH + r;
        wreg[r] = pack2(Whh[j0 * HID + k], Whh[(j0 + 1) * HID + k]);
    }
#pragma unroll
    for (int i = 0; i < 2; i++) hsm[tid + 512 * i] = 0.0f;

    unsigned long long p0 = 0ULL, p1 = 0ULL;
    if (g == 0) {
        p0 = *reinterpret_cast<const unsigned long long*>(g_g1f + (size_t)(b0 + 0) * GATE + j0);
        p1 = *reinterpret_cast<const unsigned long long*>(g_g1f + (size_t)(b0 + 1) * GATE + j0);
    }
    const int u = tid & 127, bsel = (tid >> 7) & 1;
    const bool docell = tid < 256;
    float c = 0.0f;
    const float* wp = Wsm + g * (KSMH * 512) + j0;
    __syncthreads();

    for (int s = 0; s < TT_; s++) {
        const int pb = s & 1;
        unsigned long long acc0 = p0, acc1 = p1;
        if (g == 0 && s + 1 < TT_) {
            size_t rn = (size_t)(s + 1) * BB_ + b0;
            p0 = *reinterpret_cast<const unsigned long long*>(g_g1f + rn * GATE + j0);
            p1 = *reinterpret_cast<const unsigned long long*>(g_g1f + (rn + 1) * GATE + j0);
        }
        const float* hb = hsm + pb * 512 + g * 256;
#pragma unroll 9
        for (int kk = 0; kk < KSMH; kk++) {
            unsigned long long w2 = *reinterpret_cast<const unsigned long long*>(wp + kk * 512);
            ulonglong2 H = *reinterpret_cast<const ulonglong2*>(hb + kk * 4);
            ffma2(acc0, w2, H.x); ffma2(acc1, w2, H.y);
        }
#pragma unroll
        for (int r = 0; r < KRGH; r++) {
            ulonglong2 H = *reinterpret_cast<const ulonglong2*>(hb + (KSMH + r) * 4);
            ffma2(acc0, wreg[r], H.x); ffma2(acc1, wreg[r], H.y);
        }
        *reinterpret_cast<unsigned long long*>(gsm + g * 1024 + j0) = acc0;
        *reinterpret_cast<unsigned long long*>(gsm + g * 1024 + 512 + j0) = acc1;
        __syncthreads();
        if (docell) {
            const float* ga = gsm + bsel * 512;
            const float* gb2 = gsm + 1024 + bsel * 512;
            float gi = ga[u] + gb2[u], gf = ga[u + 128] + gb2[u + 128];
            float gg = ga[u + 256] + gb2[u + 256], go = ga[u + 384] + gb2[u + 384];
            c = sigm_f(gf) * c + sigm_f(gi) * tanh_f(gg);
            float h = sigm_f(go) * tanh_f(c);
            *reinterpret_cast<float2*>(hsm + (pb ^ 1) * 512 + u * 4 + bsel * 2) = make_float2(h, h);
            if (s == TT_ - 1) g_h2f[(b0 + bsel) * HID + u] = h;
        }
        __syncthreads();
    }
}

// ============ Kernel 4: layer-1 backward one step + FC (measured-pass) ============
extern "C" __global__ void __launch_bounds__(512, 1)
final_k(const float* __restrict__ Wihb, const float* __restrict__ bvb,
        const float* __restrict__ Wfc,  const float* __restrict__ bfc,
        float* __restrict__ out)
{
    __shared__ float h1s[1024], hfs[512], gates[2048], hbs[512];
    const int tid = threadIdx.x, b0 = blockIdx.x * 4;

    for (int idx = tid; idx < 1024; idx += 512) {
        int r = idx >> 8, k = idx & 255;
        h1s[idx] = g_h1[((size_t)(TT_ - 1) * BB_ + b0 + r) * 256 + k];
    }
    if (tid < 512) hfs[tid] = g_h2f[b0 * HID + tid];
    __syncthreads();

    float acc[4];
    const float bj = bvb[tid];
#pragma unroll
    for (int r = 0; r < 4; r++) acc[r] = bj;
    const float* wr = Wihb + (size_t)tid * 256;
#pragma unroll 4
    for (int k = 0; k < 256; k++) {
        float w = wr[k];
#pragma unroll
        for (int r = 0; r < 4; r++) acc[r] = fmaf(h1s[r * 256 + k], w, acc[r]);
    }
#pragma unroll
    for (int r = 0; r < 4; r++) gates[r * 512 + tid] = acc[r];
    __syncthreads();
    {
        int r = tid >> 7, u = tid & 127;
        float c = sigm_f(gates[r * 512 + u]) * tanh_f(gates[r * 512 + u + 256]);
        hbs[r * 128 + u] = sigm_f(gates[r * 512 + u + 384]) * tanh_f(c);
    }
    __syncthreads();
    if (tid < 24) {
        int r = tid / 6, o = tid % 6;
        const float* wf = Wfc + o * 256;
        float s0 = bfc[o], s1 = 0.0f;
#pragma unroll 4
        for (int jj = 0; jj < 128; jj++) {
            s0 = fmaf(hfs[r * 128 + jj], wf[jj], s0);
            s1 = fmaf(hbs[r * 128 + jj], wf[128 + jj], s1);
        }
        out[(b0 + r) * 6 + o] = s0 + s1;
    }
}

extern "C" void kernel_launch(void* const* d_in, const int* in_sizes, int n_in,
                              void* d_out, int out_size)
{
    (void)in_sizes; (void)n_in; (void)out_size;
    const float* x     = (const float*)d_in[0];
    const float* Wih0f = (const float*)d_in[1];
    const float* Whh0f = (const float*)d_in[2];
    const float* b0f   = (const float*)d_in[3];
    const float* Wih0b = (const float*)d_in[4];
    const float* Whh0b = (const float*)d_in[5];
    const float* b0b   = (const float*)d_in[6];
    const float* Wih1f = (const float*)d_in[7];
    const float* Whh1f = (const float*)d_in[8];
    const float* b1f   = (const float*)d_in[9];
    const float* Wih1b = (const float*)d_in[10];
    const float* Whh1b = (const float*)d_in[11];
    const float* b1b   = (const float*)d_in[12];
    const float* Wfc   = (const float*)d_in[13];
    const float* bfc   = (const float*)d_in[14];
    float* out = (float*)d_out;

    const int SM_L0 = L0_SM;                                       // 189,440 B
    const int SM_G  = (2 * 128 * WPB + 2 * 64 * WPB) * 2 + 512;    // 203,264 B
    const int SM_L1 = (2 * KSMH * 512 + 1024 + 2048) * 4;          // 159,744 B

    cudaFuncSetAttribute(lstm_l0,   cudaFuncAttributeMaxDynamicSharedMemorySize, SM_L0);
    cudaFuncSetAttribute(gemm_l1in, cudaFuncAttributeMaxDynamicSharedMemorySize, SM_G);
    cudaFuncSetAttribute(lstm_l1,   cudaFuncAttributeMaxDynamicSharedMemorySize, SM_L1);

    lstm_l0<<<dim3(64, 2), 512, SM_L0>>>(x, Wih0f, Whh0f, b0f, Wih0b, Whh0b, b0b);
    gemm_l1in<<<148, 512, SM_G>>>(Wih1f, b1f);
    lstm_l1<<<128, 512, SM_L1>>>(Whh1f);
    final_k<<<64, 512>>>(Wih1b, b1b, Wfc, bfc, out);
}

// round 14
// speedup vs baseline: 1.0978x; 1.0014x over previous
#include <cuda_runtime.h>
#include <cuda_bf16.h>
#include <cstdint>
#include <cstddef>

#define TT_   512
#define BB_   256
#define HID   128
#define GATE  512
#define KSMH  36
#define KRGH  28

// h1 stored as bf16x2 hi/lo u32 arrays: [t*256+b][kp], kp = dir*64 + u/2 (k = 2*kp, 2*kp+1)
__device__ uint32_t g_hhi[(size_t)TT_ * BB_ * 128];
__device__ uint32_t g_hlo[(size_t)TT_ * BB_ * 128];
__device__ float    g_g1f[(size_t)TT_ * BB_ * GATE];
__device__ float    g_h2f[BB_ * HID];

__device__ __forceinline__ unsigned long long pack2(float lo, float hi) {
    unsigned long long r; asm("mov.b64 %0, {%1, %2};" : "=l"(r) : "f"(lo), "f"(hi)); return r;
}
__device__ __forceinline__ void ffma2(unsigned long long& d, unsigned long long a, unsigned long long b) {
    asm("fma.rn.f32x2 %0, %1, %2, %0;" : "+l"(d) : "l"(a), "l"(b));
}
__device__ __forceinline__ float sigm_f(float x) { return __fdividef(1.0f, 1.0f + __expf(-x)); }
__device__ __forceinline__ float tanh_f(float x) {
    float a = fabsf(x), e = __expf(-2.0f * a);
    return copysignf(__fdividef(1.0f - e, 1.0f + e), x);
}
// split (f0,f1) -> bf16x2 hi {lo-half=f0} + bf16x2 residual
__device__ __forceinline__ void bsplit(float f0, float f1, uint32_t& h2, uint32_t& l2) {
    asm("cvt.rn.bf16x2.f32 %0, %1, %2;" : "=r"(h2) : "f"(f1), "f"(f0));
    float r0 = f0 - __uint_as_float(h2 << 16);
    float r1 = f1 - __uint_as_float(h2 & 0xffff0000u);
    asm("cvt.rn.bf16x2.f32 %0, %1, %2;" : "=r"(l2) : "f"(r1), "f"(r0));
}
__device__ __forceinline__ void mma16816(float* d, uint32_t a0, uint32_t a1, uint32_t a2, uint32_t a3,
                                         uint32_t b0, uint32_t b1) {
    asm volatile("mma.sync.aligned.m16n8k16.row.col.f32.bf16.bf16.f32 "
                 "{%0,%1,%2,%3}, {%4,%5,%6,%7}, {%8,%9}, {%0,%1,%2,%3};"
                 : "+f"(d[0]), "+f"(d[1]), "+f"(d[2]), "+f"(d[3])
                 : "r"(a0), "r"(a1), "r"(a2), "r"(a3), "r"(b0), "r"(b1));
}

// ============ Kernel 1: layer-0 recurrence — MMA + register-local cells ============
#define L0_XS 0
#define L0_WI 24576
#define L0_WH 32768
#define L0_AB 172032
#define L0_SM 189440

extern "C" __global__ void __launch_bounds__(512, 1)
lstm_l0(const float* __restrict__ x,
        const float* __restrict__ Wih_f, const float* __restrict__ Whh_f, const float* __restrict__ bv_f,
        const float* __restrict__ Wih_b, const float* __restrict__ Whh_b, const float* __restrict__ bv_b)
{
    extern __shared__ char smraw[];
    float*    xsm  = reinterpret_cast<float*>(smraw + L0_XS);
    float*    wihs = reinterpret_cast<float*>(smraw + L0_WI);
    uint32_t* Whi  = reinterpret_cast<uint32_t*>(smraw + L0_WH);
    uint32_t* Abuf = reinterpret_cast<uint32_t*>(smraw + L0_AB);

    const int tid = threadIdx.x;
    const int dir = blockIdx.y, b0 = blockIdx.x * 4;
    const float* __restrict__ Wih = dir ? Wih_b : Wih_f;
    const float* __restrict__ Whh = dir ? Whh_b : Whh_f;
    const float* __restrict__ bv  = dir ? bv_b  : bv_f;

    const int wid = tid >> 5, lane = tid & 31;
    const int gid = lane >> 2, tig = lane & 3;
    const int u0 = wid * 8 + tig * 2;

    for (int idx = tid; idx < 512 * 64; idx += 512) {
        int j = idx >> 6, kp = idx & 63;
        float2 w = *reinterpret_cast<const float2*>(Whh + j * 128 + kp * 2);
        uint32_t h2, l2; bsplit(w.x, w.y, h2, l2);
        Whi[j * 68 + kp] = h2;
    }
    uint32_t wlo[4][8][2];
#pragma unroll
    for (int q = 0; q < 4; q++) {
        const float* wr = Whh + (q * 128 + wid * 8 + gid) * 128;
#pragma unroll
        for (int ks = 0; ks < 8; ks++) {
            int k = ks * 16 + tig * 2;
            float2 wa = *reinterpret_cast<const float2*>(wr + k);
            float2 wb = *reinterpret_cast<const float2*>(wr + k + 8);
            uint32_t h2, l2;
            bsplit(wa.x, wa.y, h2, l2); wlo[q][ks][0] = l2;
            bsplit(wb.x, wb.y, h2, l2); wlo[q][ks][1] = l2;
        }
    }
    wihs[tid * 4 + 0] = Wih[tid * 3 + 0];
    wihs[tid * 4 + 1] = Wih[tid * 3 + 1];
    wihs[tid * 4 + 2] = Wih[tid * 3 + 2];
    wihs[tid * 4 + 3] = bv[tid];
    for (int idx = tid; idx < 6144; idx += 512) {
        int r = idx / 1536, rem = idx - r * 1536;
        xsm[(rem / 3) * 12 + r * 3 + (rem % 3)] = x[(size_t)(b0 + r) * 1536 + rem];
    }
    for (int idx = tid; idx < 2 * 2 * 16 * 68; idx += 512) Abuf[idx] = 0u;

    float c0 = 0.0f, c1 = 0.0f;
    __syncthreads();

    for (int s = 0; s < TT_; s++) {
        const int tcur = dir ? (TT_ - 1 - s) : s;
        const int pb = s & 1;
        const uint32_t* Ah = Abuf + pb * 2176;
        const uint32_t* Al = Ah + 1088;

        float acc[4][4];
#pragma unroll
        for (int q = 0; q < 4; q++) { acc[q][0] = acc[q][1] = acc[q][2] = acc[q][3] = 0.0f; }
#pragma unroll
        for (int ks = 0; ks < 8; ks++) {
            const int abase = gid * 68 + ks * 8 + tig;
            uint32_t ah0 = Ah[abase],     ah1 = Ah[abase + 544];
            uint32_t ah2 = Ah[abase + 4], ah3 = Ah[abase + 548];
            uint32_t al0 = Al[abase],     al1 = Al[abase + 544];
            uint32_t al2 = Al[abase + 4], al3 = Al[abase + 548];
#pragma unroll
            for (int q = 0; q < 4; q++) {
                const int bbase = (q * 128 + wid * 8 + gid) * 68 + ks * 8 + tig;
                uint32_t bh0 = Whi[bbase], bh1 = Whi[bbase + 4];
                mma16816(acc[q], ah0, ah1, ah2, ah3, bh0, bh1);
                mma16816(acc[q], al0, al1, al2, al3, bh0, bh1);
                mma16816(acc[q], ah0, ah1, ah2, ah3, wlo[q][ks][0], wlo[q][ks][1]);
            }
        }

        if (gid < 4) {
            const float* xp = xsm + tcur * 12 + gid * 3;
            float x0 = xp[0], x1 = xp[1], x2 = xp[2];
            float pre[4][2];
#pragma unroll
            for (int q = 0; q < 4; q++) {
                int j = q * 128 + u0;
                float4 w0 = *reinterpret_cast<const float4*>(wihs + j * 4);
                float4 w1 = *reinterpret_cast<const float4*>(wihs + (j + 1) * 4);
                pre[q][0] = acc[q][0] + fmaf(w0.x, x0, fmaf(w0.y, x1, fmaf(w0.z, x2, w0.w)));
                pre[q][1] = acc[q][1] + fmaf(w1.x, x0, fmaf(w1.y, x1, fmaf(w1.z, x2, w1.w)));
            }
            c0 = sigm_f(pre[1][0]) * c0 + sigm_f(pre[0][0]) * tanh_f(pre[2][0]);
            float h0 = sigm_f(pre[3][0]) * tanh_f(c0);
            c1 = sigm_f(pre[1][1]) * c1 + sigm_f(pre[0][1]) * tanh_f(pre[2][1]);
            float h1 = sigm_f(pre[3][1]) * tanh_f(c1);

            uint32_t h2, l2; bsplit(h0, h1, h2, l2);
            uint32_t* AhN = Abuf + (pb ^ 1) * 2176;
            AhN[gid * 68 + (u0 >> 1)]        = h2;
            AhN[1088 + gid * 68 + (u0 >> 1)] = l2;
            // h1 in bf16 hi/lo format (consumed by gemm fragments + final_k)
            size_t gidx = ((size_t)tcur * BB_ + b0 + gid) * 128 + dir * 64 + (u0 >> 1);
            g_hhi[gidx] = h2;
            g_hlo[gidx] = l2;
        }
        __syncthreads();
    }
}

// ============ Kernel 2: GEMM — bf16 MMA; A arrives pre-split (u32 copy, no cvt) ============
#define WP32 132   // u32 pitch (132 % 32 == 4 -> conflict-free fragment reads)
extern "C" __global__ void __launch_bounds__(512, 1)
gemm_l1in(const float* __restrict__ W, const float* __restrict__ bias)
{
    extern __shared__ uint32_t smg[];
    uint32_t* Whi = smg;                     // [128][WP32]
    uint32_t* Wlo = Whi + 128 * WP32;
    uint32_t* Ahi = Wlo + 128 * WP32;        // [64][WP32]
    uint32_t* Alo = Ahi + 64 * WP32;
    float* biasS  = reinterpret_cast<float*>(Alo + 64 * WP32);

    const int tid = threadIdx.x;
    const int jblk = blockIdx.x & 3, tg = blockIdx.x >> 2;

    for (int idx = tid; idx < 128 * 128; idx += 512) {
        int jj = idx >> 7, kp = idx & 127;
        float2 w = *reinterpret_cast<const float2*>(W + ((size_t)(jblk * 128 + jj)) * 256 + 2 * kp);
        uint32_t h2, l2; bsplit(w.x, w.y, h2, l2);
        Whi[jj * WP32 + kp] = h2;
        Wlo[jj * WP32 + kp] = l2;
    }
    if (tid < 128) biasS[tid] = bias[jblk * 128 + tid];

    const int wid = tid >> 5, lane = tid & 31;
    const int wm = wid >> 2, wn = wid & 3;        // 4 m-blocks x 4 n-blocks
    const int m0 = wm * 16, n0 = wn * 32;
    const int gid = lane >> 2, tig = lane & 3;
    __syncthreads();

    for (int tile = tg; tile < 2048; tile += 37) {
        const size_t r0 = (size_t)tile * 64;
        // A tiles: straight u32 copies (uint4), 4 iters per array per thread
        for (int idx = tid; idx < 64 * 32; idx += 512) {
            int row = idx >> 5, kc = idx & 31;
            uint4 vh = *reinterpret_cast<const uint4*>(g_hhi + (r0 + row) * 128 + kc * 4);
            uint4 vl = *reinterpret_cast<const uint4*>(g_hlo + (r0 + row) * 128 + kc * 4);
            *reinterpret_cast<uint4*>(Ahi + row * WP32 + kc * 4) = vh;
            *reinterpret_cast<uint4*>(Alo + row * WP32 + kc * 4) = vl;
        }
        __syncthreads();

        float acc[4][4];
#pragma unroll
        for (int nf = 0; nf < 4; nf++) {
            float bv0 = biasS[n0 + nf * 8 + tig * 2], bv1 = biasS[n0 + nf * 8 + tig * 2 + 1];
            acc[nf][0] = bv0; acc[nf][1] = bv1; acc[nf][2] = bv0; acc[nf][3] = bv1;
        }
#pragma unroll 4
        for (int ks = 0; ks < 16; ks++) {
            const int abase = (m0 + gid) * WP32 + ks * 8 + tig;
            uint32_t ah0 = Ahi[abase],     ah1 = Ahi[abase + 8 * WP32];
            uint32_t ah2 = Ahi[abase + 4], ah3 = Ahi[abase + 8 * WP32 + 4];
            uint32_t al0 = Alo[abase],     al1 = Alo[abase + 8 * WP32];
            uint32_t al2 = Alo[abase + 4], al3 = Alo[abase + 8 * WP32 + 4];
#pragma unroll
            for (int nf = 0; nf < 4; nf++) {
                const int bbase = (n0 + nf * 8 + gid) * WP32 + ks * 8 + tig;
                uint32_t bh0 = Whi[bbase], bh1 = Whi[bbase + 4];
                uint32_t bl0 = Wlo[bbase], bl1 = Wlo[bbase + 4];
                mma16816(acc[nf], ah0, ah1, ah2, ah3, bh0, bh1);
                mma16816(acc[nf], al0, al1, al2, al3, bh0, bh1);
                mma16816(acc[nf], ah0, ah1, ah2, ah3, bl0, bl1);
            }
        }
        const size_t row = r0 + m0 + gid;
        const int col = jblk * 128 + n0 + tig * 2;
#pragma unroll
        for (int nf = 0; nf < 4; nf++) {
            *reinterpret_cast<float2*>(g_g1f + row * GATE + col + nf * 8) =
                make_float2(acc[nf][0], acc[nf][1]);
            *reinterpret_cast<float2*>(g_g1f + (row + 8) * GATE + col + nf * 8) =
                make_float2(acc[nf][2], acc[nf][3]);
        }
        __syncthreads();
    }
}

// ============ Kernel 3: layer-1 recurrence — FFMA2 split-k (measured-2799 cfg) ============
extern "C" __global__ void __launch_bounds__(512, 1)
lstm_l1(const float* __restrict__ Whh)
{
    extern __shared__ float sm1[];
    float* Wsm = sm1;
    float* hsm = sm1 + 2 * KSMH * 512;
    float* gsm = hsm + 1024;

    const int tid = threadIdx.x, g = tid >> 8, t = tid & 255, j0 = 2 * t;
    const int b0 = blockIdx.x * 2;

    for (int idx = tid; idx < 2 * KSMH * 512; idx += 512) {
        int gg = idx / (KSMH * 512), rem = idx - gg * (KSMH * 512);
        Wsm[idx] = Whh[(rem & 511) * HID + gg * 64 + (rem >> 9)];
    }
    unsigned long long wreg[KRGH];
#pragma unroll
    for (int r = 0; r < KRGH; r++) {
        int k = g * 64 + KSMH + r;
        wreg[r] = pack2(Whh[j0 * HID + k], Whh[(j0 + 1) * HID + k]);
    }
#pragma unroll
    for (int i = 0; i < 2; i++) hsm[tid + 512 * i] = 0.0f;

    unsigned long long p0 = 0ULL, p1 = 0ULL;
    if (g == 0) {
        p0 = *reinterpret_cast<const unsigned long long*>(g_g1f + (size_t)(b0 + 0) * GATE + j0);
        p1 = *reinterpret_cast<const unsigned long long*>(g_g1f + (size_t)(b0 + 1) * GATE + j0);
    }
    const int u = tid & 127, bsel = (tid >> 7) & 1;
    const bool docell = tid < 256;
    float c = 0.0f;
    const float* wp = Wsm + g * (KSMH * 512) + j0;
    __syncthreads();

    for (int s = 0; s < TT_; s++) {
        const int pb = s & 1;
        unsigned long long acc0 = p0, acc1 = p1;
        if (g == 0 && s + 1 < TT_) {
            size_t rn = (size_t)(s + 1) * BB_ + b0;
            p0 = *reinterpret_cast<const unsigned long long*>(g_g1f + rn * GATE + j0);
            p1 = *reinterpret_cast<const unsigned long long*>(g_g1f + (rn + 1) * GATE + j0);
        }
        const float* hb = hsm + pb * 512 + g * 256;
#pragma unroll 9
        for (int kk = 0; kk < KSMH; kk++) {
            unsigned long long w2 = *reinterpret_cast<const unsigned long long*>(wp + kk * 512);
            ulonglong2 H = *reinterpret_cast<const ulonglong2*>(hb + kk * 4);
            ffma2(acc0, w2, H.x); ffma2(acc1, w2, H.y);
        }
#pragma unroll
        for (int r = 0; r < KRGH; r++) {
            ulonglong2 H = *reinterpret_cast<const ulonglong2*>(hb + (KSMH + r) * 4);
            ffma2(acc0, wreg[r], H.x); ffma2(acc1, wreg[r], H.y);
        }
        *reinterpret_cast<unsigned long long*>(gsm + g * 1024 + j0) = acc0;
        *reinterpret_cast<unsigned long long*>(gsm + g * 1024 + 512 + j0) = acc1;
        __syncthreads();
        if (docell) {
            const float* ga = gsm + bsel * 512;
            const float* gb2 = gsm + 1024 + bsel * 512;
            float gi = ga[u] + gb2[u], gf = ga[u + 128] + gb2[u + 128];
            float gg = ga[u + 256] + gb2[u + 256], go = ga[u + 384] + gb2[u + 384];
            c = sigm_f(gf) * c + sigm_f(gi) * tanh_f(gg);
            float h = sigm_f(go) * tanh_f(c);
            *reinterpret_cast<float2*>(hsm + (pb ^ 1) * 512 + u * 4 + bsel * 2) = make_float2(h, h);
            if (s == TT_ - 1) g_h2f[(b0 + bsel) * HID + u] = h;
        }
        __syncthreads();
    }
}

// ============ Kernel 4: layer-1 backward one step + FC (h1 reconstructed hi+lo) ============
extern "C" __global__ void __launch_bounds__(512, 1)
final_k(const float* __restrict__ Wihb, const float* __restrict__ bvb,
        const float* __restrict__ Wfc,  const float* __restrict__ bfc,
        float* __restrict__ out)
{
    __shared__ float h1s[1024], hfs[512], gates[2048], hbs[512];
    const int tid = threadIdx.x, b0 = blockIdx.x * 4;

    {   // reconstruct fp32 h1[T-1] from bf16 hi+lo pairs: 4 rows x 128 u32
        int r = tid >> 7, kp = tid & 127;
        size_t gidx = ((size_t)(TT_ - 1) * BB_ + b0 + r) * 128 + kp;
        uint32_t h2 = g_hhi[gidx], l2 = g_hlo[gidx];
        h1s[r * 256 + 2 * kp]     = __uint_as_float(h2 << 16) + __uint_as_float(l2 << 16);
        h1s[r * 256 + 2 * kp + 1] = __uint_as_float(h2 & 0xffff0000u) + __uint_as_float(l2 & 0xffff0000u);
    }
    if (tid < 512) hfs[tid] = g_h2f[b0 * HID + tid];
    __syncthreads();

    float acc[4];
    const float bj = bvb[tid];
#pragma unroll
    for (int r = 0; r < 4; r++) acc[r] = bj;
    const float* wr = Wihb + (size_t)tid * 256;
#pragma unroll 4
    for (int k = 0; k < 256; k++) {
        float w = wr[k];
#pragma unroll
        for (int r = 0; r < 4; r++) acc[r] = fmaf(h1s[r * 256 + k], w, acc[r]);
    }
#pragma unroll
    for (int r = 0; r < 4; r++) gates[r * 512 + tid] = acc[r];
    __syncthreads();
    {
        int r = tid >> 7, u = tid & 127;
        float c = sigm_f(gates[r * 512 + u]) * tanh_f(gates[r * 512 + u + 256]);
        hbs[r * 128 + u] = sigm_f(gates[r * 512 + u + 384]) * tanh_f(c);
    }
    __syncthreads();
    if (tid < 24) {
        int r = tid / 6, o = tid % 6;
        const float* wf = Wfc + o * 256;
        float s0 = bfc[o], s1 = 0.0f;
#pragma unroll 4
        for (int jj = 0; jj < 128; jj++) {
            s0 = fmaf(hfs[r * 128 + jj], wf[jj], s0);
            s1 = fmaf(hbs[r * 128 + jj], wf[128 + jj], s1);
        }
        out[(b0 + r) * 6 + o] = s0 + s1;
    }
}

extern "C" void kernel_launch(void* const* d_in, const int* in_sizes, int n_in,
                              void* d_out, int out_size)
{
    (void)in_sizes; (void)n_in; (void)out_size;
    const float* x     = (const float*)d_in[0];
    const float* Wih0f = (const float*)d_in[1];
    const float* Whh0f = (const float*)d_in[2];
    const float* b0f   = (const float*)d_in[3];
    const float* Wih0b = (const float*)d_in[4];
    const float* Whh0b = (const float*)d_in[5];
    const float* b0b   = (const float*)d_in[6];
    const float* Wih1f = (const float*)d_in[7];
    const float* Whh1f = (const float*)d_in[8];
    const float* b1f   = (const float*)d_in[9];
    const float* Wih1b = (const float*)d_in[10];
    const float* Whh1b = (const float*)d_in[11];
    const float* b1b   = (const float*)d_in[12];
    const float* Wfc   = (const float*)d_in[13];
    const float* bfc   = (const float*)d_in[14];
    float* out = (float*)d_out;

    const int SM_L0 = L0_SM;                                   // 189,440 B
    const int SM_G  = (2 * 128 * WP32 + 2 * 64 * WP32) * 4 + 512;   // 203,264 B
    const int SM_L1 = (2 * KSMH * 512 + 1024 + 2048) * 4;      // 159,744 B

    cudaFuncSetAttribute(lstm_l0,   cudaFuncAttributeMaxDynamicSharedMemorySize, SM_L0);
    cudaFuncSetAttribute(gemm_l1in, cudaFuncAttributeMaxDynamicSharedMemorySize, SM_G);
    cudaFuncSetAttribute(lstm_l1,   cudaFuncAttributeMaxDynamicSharedMemorySize, SM_L1);

    lstm_l0<<<dim3(64, 2), 512, SM_L0>>>(x, Wih0f, Whh0f, b0f, Wih0b, Whh0b, b0b);
    gemm_l1in<<<148, 512, SM_G>>>(Wih1f, b1f);
    lstm_l1<<<128, 512, SM_L1>>>(Whh1f);
    final_k<<<64, 512>>>(Wih1b, b1b, Wfc, bfc, out);
}

// round 16
// speedup vs baseline: 1.2173x; 1.1088x over previous
#include <cuda_runtime.h>
#include <cuda_bf16.h>
#include <cstdint>
#include <cstddef>

#define TT_   512
#define BB_   256
#define HID   128
#define GATE  512
#define KSMH  36
#define KRGH  28

// h1 stored as bf16x2 hi/lo u32 arrays: [t*256+b][kp], kp = dir*64 + u/2
__device__ uint32_t g_hhi[(size_t)TT_ * BB_ * 128];
__device__ uint32_t g_hlo[(size_t)TT_ * BB_ * 128];
__device__ float    g_g1f[(size_t)TT_ * BB_ * GATE];
__device__ float    g_h2f[BB_ * HID];

__device__ __forceinline__ unsigned long long pack2(float lo, float hi) {
    unsigned long long r; asm("mov.b64 %0, {%1, %2};" : "=l"(r) : "f"(lo), "f"(hi)); return r;
}
__device__ __forceinline__ void ffma2(unsigned long long& d, unsigned long long a, unsigned long long b) {
    asm("fma.rn.f32x2 %0, %1, %2, %0;" : "+l"(d) : "l"(a), "l"(b));
}
__device__ __forceinline__ float sigm_f(float x) { return __fdividef(1.0f, 1.0f + __expf(-x)); }
__device__ __forceinline__ float tanh_f(float x) {
    float a = fabsf(x), e = __expf(-2.0f * a);
    return copysignf(__fdividef(1.0f - e, 1.0f + e), x);
}
// split (f0,f1) -> bf16x2 hi {lo-half=f0} + bf16x2 residual
__device__ __forceinline__ void bsplit(float f0, float f1, uint32_t& h2, uint32_t& l2) {
    asm("cvt.rn.bf16x2.f32 %0, %1, %2;" : "=r"(h2) : "f"(f1), "f"(f0));
    float r0 = f0 - __uint_as_float(h2 << 16);
    float r1 = f1 - __uint_as_float(h2 & 0xffff0000u);
    asm("cvt.rn.bf16x2.f32 %0, %1, %2;" : "=r"(l2) : "f"(r1), "f"(r0));
}
__device__ __forceinline__ void mma16816(float* d, uint32_t a0, uint32_t a1, uint32_t a2, uint32_t a3,
                                         uint32_t b0, uint32_t b1) {
    asm volatile("mma.sync.aligned.m16n8k16.row.col.f32.bf16.bf16.f32 "
                 "{%0,%1,%2,%3}, {%4,%5,%6,%7}, {%8,%9}, {%0,%1,%2,%3};"
                 : "+f"(d[0]), "+f"(d[1]), "+f"(d[2]), "+f"(d[3])
                 : "r"(a0), "r"(a1), "r"(a2), "r"(a3), "r"(b0), "r"(b1));
}

// ============ Kernel 1: layer-0 — 2-PASS hi/lo ROW-PACKED MMA ============
// A tile [16][68]: rows 0-3 = Ahi (4 batch rows), rows 8-11 = Alo, rest zero.
// Pass1 (Whi): rows get Ahi*Whi / Alo*Whi.  Pass2 (Wlo): Ahi*Wlo / Alo*Wlo.
// Epilogue sums row gid + row gid+8 accs -> EXACT 4-term product, 64 HMMA/warp/step.
#define L0_XS 0
#define L0_WI 24576
#define L0_WH 32768                   // Whi u32 [512][68] = 139264 B
#define L0_AB 172032                  // A bufs [2][16][68] u32 = 8704 B
#define L0_SM 180736

extern "C" __global__ void __launch_bounds__(512, 1)
lstm_l0(const float* __restrict__ x,
        const float* __restrict__ Wih_f, const float* __restrict__ Whh_f, const float* __restrict__ bv_f,
        const float* __restrict__ Wih_b, const float* __restrict__ Whh_b, const float* __restrict__ bv_b)
{
    extern __shared__ char smraw[];
    float*    xsm  = reinterpret_cast<float*>(smraw + L0_XS);
    float*    wihs = reinterpret_cast<float*>(smraw + L0_WI);
    uint32_t* Whi  = reinterpret_cast<uint32_t*>(smraw + L0_WH);
    uint32_t* Abuf = reinterpret_cast<uint32_t*>(smraw + L0_AB);   // [pb][16][68]

    const int tid = threadIdx.x;
    const int dir = blockIdx.y, b0 = blockIdx.x * 4;
    const float* __restrict__ Wih = dir ? Wih_b : Wih_f;
    const float* __restrict__ Whh = dir ? Whh_b : Whh_f;
    const float* __restrict__ bv  = dir ? bv_b  : bv_f;

    const int wid = tid >> 5, lane = tid & 31;
    const int gid = lane >> 2, tig = lane & 3;
    const int u0 = wid * 8 + tig * 2;

    for (int idx = tid; idx < 512 * 64; idx += 512) {
        int j = idx >> 6, kp = idx & 63;
        float2 w = *reinterpret_cast<const float2*>(Whh + j * 128 + kp * 2);
        uint32_t h2, l2; bsplit(w.x, w.y, h2, l2);
        Whi[j * 68 + kp] = h2;
    }
    uint32_t wlo[4][8][2];
#pragma unroll
    for (int q = 0; q < 4; q++) {
        const float* wr = Whh + (q * 128 + wid * 8 + gid) * 128;
#pragma unroll
        for (int ks = 0; ks < 8; ks++) {
            int k = ks * 16 + tig * 2;
            float2 wa = *reinterpret_cast<const float2*>(wr + k);
            float2 wb = *reinterpret_cast<const float2*>(wr + k + 8);
            uint32_t h2, l2;
            bsplit(wa.x, wa.y, h2, l2); wlo[q][ks][0] = l2;
            bsplit(wb.x, wb.y, h2, l2); wlo[q][ks][1] = l2;
        }
    }
    wihs[tid * 4 + 0] = Wih[tid * 3 + 0];
    wihs[tid * 4 + 1] = Wih[tid * 3 + 1];
    wihs[tid * 4 + 2] = Wih[tid * 3 + 2];
    wihs[tid * 4 + 3] = bv[tid];
    for (int idx = tid; idx < 6144; idx += 512) {
        int r = idx / 1536, rem = idx - r * 1536;
        xsm[(rem / 3) * 12 + r * 3 + (rem % 3)] = x[(size_t)(b0 + r) * 1536 + rem];
    }
    for (int idx = tid; idx < 2 * 16 * 68; idx += 512) Abuf[idx] = 0u;

    float c0 = 0.0f, c1 = 0.0f;
    __syncthreads();

    for (int s = 0; s < TT_; s++) {
        const int tcur = dir ? (TT_ - 1 - s) : s;
        const int pb = s & 1;
        const uint32_t* A = Abuf + pb * 1088;

        float acc[4][4];
#pragma unroll
        for (int q = 0; q < 4; q++) { acc[q][0] = acc[q][1] = acc[q][2] = acc[q][3] = 0.0f; }
#pragma unroll
        for (int ks = 0; ks < 8; ks++) {
            const int abase = gid * 68 + ks * 8 + tig;
            uint32_t a0 = A[abase];           // row gid      (Ahi)
            uint32_t a1 = A[abase + 544];     // row gid+8    (Alo)
            uint32_t a2 = A[abase + 4];
            uint32_t a3 = A[abase + 548];
#pragma unroll
            for (int q = 0; q < 4; q++) {
                const int bbase = (q * 128 + wid * 8 + gid) * 68 + ks * 8 + tig;
                uint32_t bh0 = Whi[bbase], bh1 = Whi[bbase + 4];
                mma16816(acc[q], a0, a1, a2, a3, bh0, bh1);                     // *Whi
                mma16816(acc[q], a0, a1, a2, a3, wlo[q][ks][0], wlo[q][ks][1]); // *Wlo
            }
        }

        if (gid < 4) {                         // 4 real rows; all 4 split terms summed
            const float* xp = xsm + tcur * 12 + gid * 3;
            float x0 = xp[0], x1 = xp[1], x2 = xp[2];
            float pre[4][2];
#pragma unroll
            for (int q = 0; q < 4; q++) {
                int j = q * 128 + u0;
                float4 w0 = *reinterpret_cast<const float4*>(wihs + j * 4);
                float4 w1 = *reinterpret_cast<const float4*>(wihs + (j + 1) * 4);
                pre[q][0] = (acc[q][0] + acc[q][2]) +
                            fmaf(w0.x, x0, fmaf(w0.y, x1, fmaf(w0.z, x2, w0.w)));
                pre[q][1] = (acc[q][1] + acc[q][3]) +
                            fmaf(w1.x, x0, fmaf(w1.y, x1, fmaf(w1.z, x2, w1.w)));
            }
            c0 = sigm_f(pre[1][0]) * c0 + sigm_f(pre[0][0]) * tanh_f(pre[2][0]);
            float h0 = sigm_f(pre[3][0]) * tanh_f(c0);
            c1 = sigm_f(pre[1][1]) * c1 + sigm_f(pre[0][1]) * tanh_f(pre[2][1]);
            float h1 = sigm_f(pre[3][1]) * tanh_f(c1);

            uint32_t h2, l2; bsplit(h0, h1, h2, l2);
            uint32_t* AN = Abuf + (pb ^ 1) * 1088;
            AN[gid * 68 + (u0 >> 1)]       = h2;     // hi -> row gid
            AN[(gid + 8) * 68 + (u0 >> 1)] = l2;     // lo -> row gid+8
            size_t gidx = ((size_t)tcur * BB_ + b0 + gid) * 128 + dir * 64 + (u0 >> 1);
            g_hhi[gidx] = h2;
            g_hlo[gidx] = l2;
        }
        __syncthreads();
    }
}

// ============ Kernel 2: GEMM — bf16 MMA, A pre-split (R14 measured-pass) ============
#define WP32 132
extern "C" __global__ void __launch_bounds__(512, 1)
gemm_l1in(const float* __restrict__ W, const float* __restrict__ bias)
{
    extern __shared__ uint32_t smg[];
    uint32_t* Whi = smg;
    uint32_t* Wlo = Whi + 128 * WP32;
    uint32_t* Ahi = Wlo + 128 * WP32;
    uint32_t* Alo = Ahi + 64 * WP32;
    float* biasS  = reinterpret_cast<float*>(Alo + 64 * WP32);

    const int tid = threadIdx.x;
    const int jblk = blockIdx.x & 3, tg = blockIdx.x >> 2;

    for (int idx = tid; idx < 128 * 128; idx += 512) {
        int jj = idx >> 7, kp = idx & 127;
        float2 w = *reinterpret_cast<const float2*>(W + ((size_t)(jblk * 128 + jj)) * 256 + 2 * kp);
        uint32_t h2, l2; bsplit(w.x, w.y, h2, l2);
        Whi[jj * WP32 + kp] = h2;
        Wlo[jj * WP32 + kp] = l2;
    }
    if (tid < 128) biasS[tid] = bias[jblk * 128 + tid];

    const int wid = tid >> 5, lane = tid & 31;
    const int wm = wid >> 2, wn = wid & 3;
    const int m0 = wm * 16, n0 = wn * 32;
    const int gid = lane >> 2, tig = lane & 3;
    __syncthreads();

    for (int tile = tg; tile < 2048; tile += 37) {
        const size_t r0 = (size_t)tile * 64;
        for (int idx = tid; idx < 64 * 32; idx += 512) {
            int row = idx >> 5, kc = idx & 31;
            uint4 vh = *reinterpret_cast<const uint4*>(g_hhi + (r0 + row) * 128 + kc * 4);
            uint4 vl = *reinterpret_cast<const uint4*>(g_hlo + (r0 + row) * 128 + kc * 4);
            *reinterpret_cast<uint4*>(Ahi + row * WP32 + kc * 4) = vh;
            *reinterpret_cast<uint4*>(Alo + row * WP32 + kc * 4) = vl;
        }
        __syncthreads();

        float acc[4][4];
#pragma unroll
        for (int nf = 0; nf < 4; nf++) {
            float bv0 = biasS[n0 + nf * 8 + tig * 2], bv1 = biasS[n0 + nf * 8 + tig * 2 + 1];
            acc[nf][0] = bv0; acc[nf][1] = bv1; acc[nf][2] = bv0; acc[nf][3] = bv1;
        }
#pragma unroll 4
        for (int ks = 0; ks < 16; ks++) {
            const int abase = (m0 + gid) * WP32 + ks * 8 + tig;
            uint32_t ah0 = Ahi[abase],     ah1 = Ahi[abase + 8 * WP32];
            uint32_t ah2 = Ahi[abase + 4], ah3 = Ahi[abase + 8 * WP32 + 4];
            uint32_t al0 = Alo[abase],     al1 = Alo[abase + 8 * WP32];
            uint32_t al2 = Alo[abase + 4], al3 = Alo[abase + 8 * WP32 + 4];
#pragma unroll
            for (int nf = 0; nf < 4; nf++) {
                const int bbase = (n0 + nf * 8 + gid) * WP32 + ks * 8 + tig;
                uint32_t bh0 = Whi[bbase], bh1 = Whi[bbase + 4];
                uint32_t bl0 = Wlo[bbase], bl1 = Wlo[bbase + 4];
                mma16816(acc[nf], ah0, ah1, ah2, ah3, bh0, bh1);
                mma16816(acc[nf], al0, al1, al2, al3, bh0, bh1);
                mma16816(acc[nf], ah0, ah1, ah2, ah3, bl0, bl1);
            }
        }
        const size_t row = r0 + m0 + gid;
        const int col = jblk * 128 + n0 + tig * 2;
#pragma unroll
        for (int nf = 0; nf < 4; nf++) {
            *reinterpret_cast<float2*>(g_g1f + row * GATE + col + nf * 8) =
                make_float2(acc[nf][0], acc[nf][1]);
            *reinterpret_cast<float2*>(g_g1f + (row + 8) * GATE + col + nf * 8) =
                make_float2(acc[nf][2], acc[nf][3]);
        }
        __syncthreads();
    }
}

// ============ Kernel 3: layer-1 recurrence — FFMA2 split-k (measured-pass) ============
extern "C" __global__ void __launch_bounds__(512, 1)
lstm_l1(const float* __restrict__ Whh)
{
    extern __shared__ float sm1[];
    float* Wsm = sm1;
    float* hsm = sm1 + 2 * KSMH * 512;
    float* gsm = hsm + 1024;

    const int tid = threadIdx.x, g = tid >> 8, t = tid & 255, j0 = 2 * t;
    const int b0 = blockIdx.x * 2;

    for (int idx = tid; idx < 2 * KSMH * 512; idx += 512) {
        int gg = idx / (KSMH * 512), rem = idx - gg * (KSMH * 512);
        Wsm[idx] = Whh[(rem & 511) * HID + gg * 64 + (rem >> 9)];
    }
    unsigned long long wreg[KRGH];
#pragma unroll
    for (int r = 0; r < KRGH; r++) {
        int k = g * 64 + KSMH + r;
        wreg[r] = pack2(Whh[j0 * HID + k], Whh[(j0 + 1) * HID + k]);
    }
#pragma unroll
    for (int i = 0; i < 2; i++) hsm[tid + 512 * i] = 0.0f;

    unsigned long long p0 = 0ULL, p1 = 0ULL;
    if (g == 0) {
        p0 = *reinterpret_cast<const unsigned long long*>(g_g1f + (size_t)(b0 + 0) * GATE + j0);
        p1 = *reinterpret_cast<const unsigned long long*>(g_g1f + (size_t)(b0 + 1) * GATE + j0);
    }
    const int u = tid & 127, bsel = (tid >> 7) & 1;
    const bool docell = tid < 256;
    float c = 0.0f;
    const float* wp = Wsm + g * (KSMH * 512) + j0;
    __syncthreads();

    for (int s = 0; s < TT_; s++) {
        const int pb = s & 1;
        unsigned long long acc0 = p0, acc1 = p1;
        if (g == 0 && s + 1 < TT_) {
            size_t rn = (size_t)(s + 1) * BB_ + b0;
            p0 = *reinterpret_cast<const unsigned long long*>(g_g1f + rn * GATE + j0);
            p1 = *reinterpret_cast<const unsigned long long*>(g_g1f + (rn + 1) * GATE + j0);
        }
        const float* hb = hsm + pb * 512 + g * 256;
#pragma unroll 9
        for (int kk = 0; kk < KSMH; kk++) {
            unsigned long long w2 = *reinterpret_cast<const unsigned long long*>(wp + kk * 512);
            ulonglong2 H = *reinterpret_cast<const ulonglong2*>(hb + kk * 4);
            ffma2(acc0, w2, H.x); ffma2(acc1, w2, H.y);
        }
#pragma unroll
        for (int r = 0; r < KRGH; r++) {
            ulonglong2 H = *reinterpret_cast<const ulonglong2*>(hb + (KSMH + r) * 4);
            ffma2(acc0, wreg[r], H.x); ffma2(acc1, wreg[r], H.y);
        }
        *reinterpret_cast<unsigned long long*>(gsm + g * 1024 + j0) = acc0;
        *reinterpret_cast<unsigned long long*>(gsm + g * 1024 + 512 + j0) = acc1;
        __syncthreads();
        if (docell) {
            const float* ga = gsm + bsel * 512;
            const float* gb2 = gsm + 1024 + bsel * 512;
            float gi = ga[u] + gb2[u], gf = ga[u + 128] + gb2[u + 128];
            float gg = ga[u + 256] + gb2[u + 256], go = ga[u + 384] + gb2[u + 384];
            c = sigm_f(gf) * c + sigm_f(gi) * tanh_f(gg);
            float h = sigm_f(go) * tanh_f(c);
            *reinterpret_cast<float2*>(hsm + (pb ^ 1) * 512 + u * 4 + bsel * 2) = make_float2(h, h);
            if (s == TT_ - 1) g_h2f[(b0 + bsel) * HID + u] = h;
        }
        __syncthreads();
    }
}

// ============ Kernel 4: layer-1 backward one step + FC (measured-pass) ============
extern "C" __global__ void __launch_bounds__(512, 1)
final_k(const float* __restrict__ Wihb, const float* __restrict__ bvb,
        const float* __restrict__ Wfc,  const float* __restrict__ bfc,
        float* __restrict__ out)
{
    __shared__ float h1s[1024], hfs[512], gates[2048], hbs[512];
    const int tid = threadIdx.x, b0 = blockIdx.x * 4;

    {
        int r = tid >> 7, kp = tid & 127;
        size_t gidx = ((size_t)(TT_ - 1) * BB_ + b0 + r) * 128 + kp;
        uint32_t h2 = g_hhi[gidx], l2 = g_hlo[gidx];
        h1s[r * 256 + 2 * kp]     = __uint_as_float(h2 << 16) + __uint_as_float(l2 << 16);
        h1s[r * 256 + 2 * kp + 1] = __uint_as_float(h2 & 0xffff0000u) + __uint_as_float(l2 & 0xffff0000u);
    }
    if (tid < 512) hfs[tid] = g_h2f[b0 * HID + tid];
    __syncthreads();

    float acc[4];
    const float bj = bvb[tid];
#pragma unroll
    for (int r = 0; r < 4; r++) acc[r] = bj;
    const float* wr = Wihb + (size_t)tid * 256;
#pragma unroll 4
    for (int k = 0; k < 256; k++) {
        float w = wr[k];
#pragma unroll
        for (int r = 0; r < 4; r++) acc[r] = fmaf(h1s[r * 256 + k], w, acc[r]);
    }
#pragma unroll
    for (int r = 0; r < 4; r++) gates[r * 512 + tid] = acc[r];
    __syncthreads();
    {
        int r = tid >> 7, u = tid & 127;
        float c = sigm_f(gates[r * 512 + u]) * tanh_f(gates[r * 512 + u + 256]);
        hbs[r * 128 + u] = sigm_f(gates[r * 512 + u + 384]) * tanh_f(c);
    }
    __syncthreads();
    if (tid < 24) {
        int r = tid / 6, o = tid % 6;
        const float* wf = Wfc + o * 256;
        float s0 = bfc[o], s1 = 0.0f;
#pragma unroll 4
        for (int jj = 0; jj < 128; jj++) {
            s0 = fmaf(hfs[r * 128 + jj], wf[jj], s0);
            s1 = fmaf(hbs[r * 128 + jj], wf[128 + jj], s1);
        }
        out[(b0 + r) * 6 + o] = s0 + s1;
    }
}

extern "C" void kernel_launch(void* const* d_in, const int* in_sizes, int n_in,
                              void* d_out, int out_size)
{
    (void)in_sizes; (void)n_in; (void)out_size;
    const float* x     = (const float*)d_in[0];
    const float* Wih0f = (const float*)d_in[1];
    const float* Whh0f = (const float*)d_in[2];
    const float* b0f   = (const float*)d_in[3];
    const float* Wih0b = (const float*)d_in[4];
    const float* Whh0b = (const float*)d_in[5];
    const float* b0b   = (const float*)d_in[6];
    const float* Wih1f = (const float*)d_in[7];
    const float* Whh1f = (const float*)d_in[8];
    const float* b1f   = (const float*)d_in[9];
    const float* Wih1b = (const float*)d_in[10];
    const float* Whh1b = (const float*)d_in[11];
    const float* b1b   = (const float*)d_in[12];
    const float* Wfc   = (const float*)d_in[13];
    const float* bfc   = (const float*)d_in[14];
    float* out = (float*)d_out;

    const int SM_L0 = L0_SM;                                        // 180,736 B
    const int SM_G  = (2 * 128 * WP32 + 2 * 64 * WP32) * 4 + 512;   // 203,264 B
    const int SM_L1 = (2 * KSMH * 512 + 1024 + 2048) * 4;           // 159,744 B

    cudaFuncSetAttribute(lstm_l0,   cudaFuncAttributeMaxDynamicSharedMemorySize, SM_L0);
    cudaFuncSetAttribute(gemm_l1in, cudaFuncAttributeMaxDynamicSharedMemorySize, SM_G);
    cudaFuncSetAttribute(lstm_l1,   cudaFuncAttributeMaxDynamicSharedMemorySize, SM_L1);

    lstm_l0<<<dim3(64, 2), 512, SM_L0>>>(x, Wih0f, Whh0f, b0f, Wih0b, Whh0b, b0b);
    gemm_l1in<<<148, 512, SM_G>>>(Wih1f, b1f);
    lstm_l1<<<128, 512, SM_L1>>>(Whh1f);
    final_k<<<64, 512>>>(Wih1b, b1b, Wfc, bfc, out);
}